// round 15
// baseline (speedup 1.0000x reference)
#include <cuda_runtime.h>
#include <math.h>

#define CCH 128
#define HW   262144         // 512*512
#define NF4  65536          // HW/4
#define SPL  3              // CTAs per channel for streaming passes
#define CHUNK 21846         // ceil(NF4/3)
#define NBIN 4096           // 12-bit prefix bins

// static scratch (allocation-free)
__device__ unsigned int g_cand[(size_t)CCH * HW];
__device__ unsigned int g_hist4k[(size_t)CCH * NBIN];     // 2MB
__device__ unsigned int g_T12[(size_t)CCH * 2048];        // u16[4096] per channel
__device__ unsigned int g_segOff[CCH * 512], g_segLen[CCH * 512], g_cursor[CCH * 512];
__device__ unsigned int g_cutBin[CCH * 256], g_cutR[CCH * 256], g_cutSlot[CCH * 256];
__device__ unsigned int g_kbA[CCH * 256], g_bSlot[CCH * 256], g_bPre[CCH * 256];
__device__ unsigned int g_kminA[CCH], g_kmaxA[CCH];
__device__ unsigned int g_nU[CCH], g_tot[CCH];
__device__ float g_partialC[CCH * SPL];
__device__ float g_chLoss[CCH];
__device__ unsigned int g_arrive = 0;

__device__ __forceinline__ unsigned int fkey(float x) {
    unsigned int u = __float_as_uint(x);
    return (u & 0x80000000u) ? ~u : (u | 0x80000000u);
}
__device__ __forceinline__ float dkey(unsigned int k) {
    return __uint_as_float((k & 0x80000000u) ? (k & 0x7fffffffu) : ~k);
}
__device__ __forceinline__ int binf(unsigned int k, float mn, float dd) {
    float v = dkey(k);
    float u = (v - mn) / dd;
    int b = (int)(u * 255.0f);
    return b < 0 ? 0 : (b > 255 ? 255 : b);
}

// ---------------- Z: zero global hist + min/max init ----------------
__global__ void zeroZ() {
    unsigned i = blockIdx.x * 1024u + threadIdx.x;          // 128*1024 = 131072
    ((uint4*)g_hist4k)[i] = make_uint4(0u, 0u, 0u, 0u);     // 2MB
    if (i < CCH) { g_kminA[i] = 0xffffffffu; g_kmaxA[i] = 0u; }
}

// ---------------- A: per-third 12-bit histogram + min/max ----------------
__global__ void __launch_bounds__(512, 3)
histA(const float* __restrict__ input, const float* __restrict__ mask)
{
    __shared__ unsigned int H[NBIN];
    __shared__ unsigned int red[32];    // [0..15] kmin, [16..31] kmax (16 warps)
    const int bid = blockIdx.x, c = bid / SPL, q = bid - c * SPL;
    const int tid = threadIdx.x, lane = tid & 31, wz = tid >> 5;
    const float4* in4 = (const float4*)(input + (size_t)c * HW);
    const float4* mk4 = (const float4*)mask;

    for (int i = tid; i < NBIN; i += 512) H[i] = 0;
    __syncthreads();

    const int start = q * CHUNK;
    const int end = min(start + CHUNK, NF4);
    unsigned kmin = 0xffffffffu, kmax = 0u;
    for (int i = start + tid; i < end; i += 512) {
        float4 a = in4[i], m = mk4[i];
        unsigned k0 = fkey(a.x * m.x), k1 = fkey(a.y * m.y);
        unsigned k2 = fkey(a.z * m.z), k3 = fkey(a.w * m.w);
        kmin = min(kmin, min(min(k0, k1), min(k2, k3)));
        kmax = max(kmax, max(max(k0, k1), max(k2, k3)));
        atomicAdd(&H[k0 >> 20], 1u);
        atomicAdd(&H[k1 >> 20], 1u);
        atomicAdd(&H[k2 >> 20], 1u);
        atomicAdd(&H[k3 >> 20], 1u);
    }
    #pragma unroll
    for (int o = 16; o; o >>= 1) {
        kmin = min(kmin, __shfl_down_sync(0xffffffffu, kmin, o));
        kmax = max(kmax, __shfl_down_sync(0xffffffffu, kmax, o));
    }
    if (lane == 0) { red[wz] = kmin; red[16 + wz] = kmax; }   // 16 warps
    __syncthreads();
    if (tid == 0) {
        unsigned mn = red[0], mx = red[16];
        for (int w = 1; w < 16; w++) { mn = min(mn, red[w]); mx = max(mx, red[16 + w]); }
        atomicMin(&g_kminA[c], mn);
        atomicMax(&g_kmaxA[c], mx);
    }
    __syncthreads();
    for (int i = tid; i < NBIN; i += 512) {
        unsigned v = H[i];
        if (v) atomicAdd(&g_hist4k[c * NBIN + i], v);   // RED (no return)
    }
}

// ---------------- B: selection per channel (12-bit) ----------------
__global__ void __launch_bounds__(1024, 1)
selB(const float* __restrict__ thist)
{
    __shared__ unsigned int HIST[NBIN];
    __shared__ unsigned int cutBin[256], cutR[256], kbA[256], bPre[256], Karr[256];
    __shared__ unsigned int uniqB[512], segOff[512], segLen[512];
    __shared__ unsigned int sgrp[65];
    __shared__ float cdf[256];
    __shared__ unsigned int red[8];

    const int c = blockIdx.x, tid = threadIdx.x;
    for (int i = tid; i < NBIN; i += 1024) HIST[i] = g_hist4k[c * NBIN + i];
    if (tid == 0) { red[0] = g_kminA[c]; red[1] = g_kmaxA[c]; }
    __syncthreads();

    if (tid >= 64 && tid < 128) {
        int g = tid - 64;
        unsigned s = 0;
        for (int w = 0; w < 64; w++) s += HIST[g * 64 + w];
        sgrp[g] = s;
    } else if (tid == 32) {
        float s = 0.0f;
        for (int j = 0; j < 256; j++) { s += thist[c * 256 + j]; cdf[j] = s; }
        float tot = s;
        for (int j = 0; j < 256; j++) {
            float t = (cdf[j] / tot) * 262144.0f;
            float f = floorf(t);
            if (f < 0.0f) f = 0.0f;
            if (f > 262144.0f) f = 262144.0f;
            Karr[j] = (unsigned)f;
        }
    }
    __syncthreads();
    if (tid == 0) {
        unsigned acc = 0;
        for (int g = 0; g < 64; g++) { unsigned t = sgrp[g]; sgrp[g] = acc; acc += t; }
        sgrp[64] = acc;
    }
    __syncthreads();

    // cut bins + boundary keys
    if (tid < 256) {
        unsigned k = Karr[tid];
        if (k == 0) { cutBin[tid] = 0xffffffffu; cutR[tid] = 0; }
        else {
            int lo = 0, hi = 63;
            while (lo < hi) { int mid = (lo + hi + 1) >> 1; if (sgrp[mid] < k) lo = mid; else hi = mid - 1; }
            unsigned acc = sgrp[lo];
            int bin = lo * 64;
            for (;; bin++) { unsigned cnt = HIST[bin]; if (acc + cnt >= k) break; acc += cnt; }
            cutBin[tid] = (unsigned)bin;
            cutR[tid] = k - acc;
        }
    } else if (tid < 511) {
        int j = tid - 255;
        unsigned mnk = red[0], mxk = red[1];
        float mn = dkey(mnk), mx = dkey(mxk);
        float dd = fmaxf(mx - mn, 1e-8f);
        if (binf(mxk, mn, dd) < j) kbA[j] = 0u;
        else {
            unsigned lo = mnk, hi = mxk;
            while (lo < hi) {
                unsigned mid = lo + ((hi - lo) >> 1);
                if (binf(mid, mn, dd) >= j) hi = mid; else lo = mid + 1;
            }
            kbA[j] = lo;
        }
    }
    __syncthreads();

    // boundary prefix counts + merge
    if (tid >= 256 && tid < 511) {
        int j = tid - 255;
        unsigned kb = kbA[j];
        if (kb != 0u) {
            unsigned p = kb >> 20, g = p >> 6;
            unsigned s = sgrp[g];
            for (unsigned b = g << 6; b < p; b++) s += HIST[b];
            bPre[j] = s;
        }
    } else if (tid == 512) {
        int i = 0, j = 1, n = 0;
        unsigned off = 0;
        for (;;) {
            unsigned a = 0xffffffffu, b = 0xffffffffu;
            while (i < 256 && cutBin[i] == 0xffffffffu) i++;
            if (i < 256) a = cutBin[i];
            while (j < 256 && kbA[j] == 0u) j++;
            if (j < 256) b = kbA[j] >> 20;
            if (a == 0xffffffffu && b == 0xffffffffu) break;
            unsigned v = min(a, b);
            while (i < 256 && cutBin[i] == v) i++;
            while (j < 256 && kbA[j] != 0u && (kbA[j] >> 20) == v) j++;
            unsigned cnt = HIST[v];
            uniqB[n] = v; segOff[n] = off; segLen[n] = cnt;
            off += cnt; n++;
        }
        red[2] = (unsigned)n;
        red[3] = off;
    }
    __syncthreads();
    const int nU = (int)red[2];

    // slots + writes
    if (tid < 256) {
        unsigned cs = 0;
        if (cutBin[tid] != 0xffffffffu) {
            unsigned p = cutBin[tid];
            int lo = 0, hi = nU - 1;
            while (lo < hi) { int mid = (lo + hi) >> 1; if (uniqB[mid] < p) lo = mid + 1; else hi = mid; }
            cs = (unsigned)lo;
        }
        g_cutBin[c * 256 + tid] = cutBin[tid];
        g_cutR[c * 256 + tid]   = cutR[tid];
        g_cutSlot[c * 256 + tid] = cs;
    } else if (tid < 511) {
        int j = tid - 255;
        unsigned bs = 0;
        if (kbA[j] != 0u) {
            unsigned p = kbA[j] >> 20;
            int lo = 0, hi = nU - 1;
            while (lo < hi) { int mid = (lo + hi) >> 1; if (uniqB[mid] < p) lo = mid + 1; else hi = mid; }
            bs = (unsigned)lo;
        }
        g_kbA[c * 256 + j]  = kbA[j];
        g_bSlot[c * 256 + j] = bs;
        g_bPre[c * 256 + j]  = bPre[j];
    } else if (tid == 511) {
        g_kbA[c * 256] = 0; g_bSlot[c * 256] = 0; g_bPre[c * 256] = 0;
        g_nU[c] = (unsigned)nU; g_tot[c] = red[3];
    }
    if (tid < 512) {
        g_segOff[c * 512 + tid] = (tid < nU) ? segOff[tid] : 0u;
        g_segLen[c * 512 + tid] = (tid < nU) ? segLen[tid] : 0u;
        g_cursor[c * 512 + tid] = 0u;
    }
    __syncthreads();

    // T12 table (4096 u16): inactive -> bm; active -> 0x8000|slot
    {
        int p0 = tid * 4;
        int lo = 0, hi = 256;
        while (lo < hi) {
            int mid = (lo + hi) >> 1;
            unsigned cl = (Karr[mid] == 0) ? 0u : cutBin[mid];
            if ((int)cl < p0) lo = mid + 1; else hi = mid;
        }
        int idx = lo;
        #pragma unroll
        for (int w = 0; w < 2; w++) {
            unsigned word = 0;
            #pragma unroll
            for (int e = 0; e < 2; e++) {
                int p = p0 + w * 2 + e;
                for (;;) {
                    if (idx >= 256) break;
                    unsigned cl = (Karr[idx] == 0) ? 0u : cutBin[idx];
                    if ((int)cl < p) idx++; else break;
                }
                word |= ((unsigned)min(idx, 255)) << (16 * e);
            }
            g_T12[c * 2048 + tid * 2 + w] = word;
        }
    }
    __syncthreads();
    if (tid < nU)
        ((unsigned short*)g_T12)[c * 4096 + uniqB[tid]] = (unsigned short)(0x8000u | (unsigned)tid);
}

// ---------------- C: fused classify -> compact / loss ----------------
__global__ void __launch_bounds__(512, 3)
passC(const float* __restrict__ input, const float* __restrict__ mask,
      const float* __restrict__ tmin_, const float* __restrict__ tmax_)
{
    __shared__ unsigned int T12s[2048];
    __shared__ unsigned int segOffS[512];
    __shared__ float fred[16];
    const int bid = blockIdx.x, c = bid / SPL, q = bid - c * SPL;
    const int tid = threadIdx.x, lane = tid & 31, wz = tid >> 5;

    for (int i = tid; i < 2048; i += 512) T12s[i] = g_T12[c * 2048 + i];
    if (tid < 512) segOffS[tid] = g_segOff[c * 512 + tid];
    __syncthreads();

    const float4* in4 = (const float4*)(input + (size_t)c * HW);
    const float4* mk4 = (const float4*)mask;
    unsigned int* candC = g_cand + (size_t)c * HW;
    unsigned int* curC = g_cursor + c * 512;
    const unsigned short* T12 = (const unsigned short*)T12s;

    const float tmn = tmin_[c];
    const float scl = tmax_[c] - tmn;
    const int start = q * CHUNK;
    const int end = min(start + CHUNK, NF4);
    float acc = 0.0f;

    for (int i = start + tid; i < end; i += 512) {
        float4 a = in4[i], m = mk4[i];
        float vv[4] = {a.x * m.x, a.y * m.y, a.z * m.z, a.w * m.w};
        #pragma unroll
        for (int e = 0; e < 4; e++) {
            float v = vv[e];
            unsigned key = fkey(v);
            unsigned t = T12[key >> 20];
            if (t & 0x8000u) {
                unsigned s = t & 0x7fffu;
                unsigned idx = atomicAdd(&curC[s], 1u);
                candC[segOffS[s] + idx] = key;
            } else {
                float bf = (float)t * (1.0f / 255.0f);
                float df = v - fmaf(bf, scl, tmn);
                acc = fmaf(df, df, acc);
            }
        }
    }
    #pragma unroll
    for (int o = 16; o; o >>= 1) acc += __shfl_down_sync(0xffffffffu, acc, o);
    if (lane == 0) fred[wz] = acc;
    __syncthreads();
    if (tid == 0) {
        float s = 0.0f;
        for (int w = 0; w < 16; w++) s += fred[w];
        g_partialC[bid] = s;
    }
}

// ---------------- D: Phase D + candidate loss + outputs + finalize ----------------
__global__ void __launch_bounds__(1024, 1)
phaseD(const float* __restrict__ tmin_, const float* __restrict__ tmax_,
       float* __restrict__ out)
{
    __shared__ unsigned int WH[8192];                 // 32 warps x 256
    __shared__ unsigned int cutBin[256], cutR[256], cutSlot[256];
    __shared__ unsigned int kbA[256], bSlot[256], bPre[256];
    __shared__ unsigned int thA[256], rankA[257];
    __shared__ unsigned int segOff[512], segLen[512];
    __shared__ float fred[32];
    __shared__ unsigned int redu[4];

    const int c = blockIdx.x, tid = threadIdx.x, lane = tid & 31, wz = tid >> 5;
    unsigned int* candC = g_cand + (size_t)c * HW;

    if (tid < 256) {
        cutBin[tid] = g_cutBin[c * 256 + tid];
        cutR[tid]   = g_cutR[c * 256 + tid];
        cutSlot[tid] = g_cutSlot[c * 256 + tid];
        kbA[tid]   = g_kbA[c * 256 + tid];
        bSlot[tid] = g_bSlot[c * 256 + tid];
        bPre[tid]  = g_bPre[c * 256 + tid];
        thA[tid] = 0u;
    }
    if (tid < 512) { segOff[tid] = g_segOff[c * 512 + tid]; segLen[tid] = g_segLen[c * 512 + tid]; }
    if (tid < 257) rankA[tid] = (tid == 0) ? 0u : (unsigned)HW;
    if (tid == 0) { redu[0] = g_tot[c]; redu[1] = g_kminA[c]; redu[2] = g_kmaxA[c]; }
    __syncthreads();

    // Phase D: warp per query
    {
        unsigned* wh = WH + wz * 256;
        for (int q = wz; q < 511; q += 32) {
            if (q < 256) {
                if (cutBin[q] == 0xffffffffu) continue;
                unsigned slot = cutSlot[q];
                unsigned off = segOff[slot], len = segLen[slot], r = cutR[q];
                unsigned known = cutBin[q];
                #pragma unroll
                for (int t = 0; t < 3; t++) {
                    const int s  = (t == 0) ? 12 : (t == 1) ? 4 : 0;
                    const int w  = (t == 2) ? 4 : 8;
                    const unsigned nb = 1u << w;
                    for (unsigned i = lane; i < nb; i += 32) wh[i] = 0;
                    __syncwarp();
                    for (unsigned i = lane; i < len; i += 32) {
                        unsigned key = candC[off + i];
                        if ((key >> (s + w)) == known)
                            atomicAdd(&wh[(key >> s) & (nb - 1u)], 1u);
                    }
                    __syncwarp();
                    unsigned sel = 0, rem = 0;
                    if (lane == 0) {
                        unsigned a2 = 0; unsigned b = 0;
                        for (;; b++) { unsigned ct = wh[b]; if (a2 + ct >= r) break; a2 += ct; }
                        sel = b; rem = r - a2;
                    }
                    sel = __shfl_sync(0xffffffffu, sel, 0);
                    rem = __shfl_sync(0xffffffffu, rem, 0);
                    known = (known << w) | sel;
                    r = rem;
                    __syncwarp();
                }
                if (lane == 0) thA[q] = known;
            } else {
                int j = q - 255;
                if (kbA[j] == 0u) continue;
                unsigned slot = bSlot[j];
                unsigned off = segOff[slot], len = segLen[slot];
                unsigned bs = kbA[j] & 0xfffffu;
                unsigned cnt = 0;
                for (unsigned i = lane; i < len; i += 32)
                    cnt += ((candC[off + i] & 0xfffffu) < bs) ? 1u : 0u;
                #pragma unroll
                for (int o = 16; o; o >>= 1) cnt += __shfl_down_sync(0xffffffffu, cnt, o);
                if (lane == 0) rankA[j] = bPre[j] + cnt;
            }
        }
    }
    __syncthreads();

    // candidate loss via thA binary search
    const float tmn = tmin_[c];
    const float scl = tmax_[c] - tmn;
    float acc = 0.0f;
    {
        const int tot = (int)redu[0];
        for (int i = tid; i < tot; i += 1024) {
            unsigned key = candC[i];
            int lo = 0, hi = 256;
            while (lo < hi) { int mid = (lo + hi) >> 1; if (thA[mid] < key) lo = mid + 1; else hi = mid; }
            int bm = min(lo, 255);
            float v = dkey(key);
            float bf = (float)bm * (1.0f / 255.0f);
            float df = v - fmaf(bf, scl, tmn);
            acc = fmaf(df, df, acc);
        }
    }

    // outputs
    if (tid < 256) out[1 + c * 256 + tid] = (float)(rankA[tid + 1] - rankA[tid]);

    #pragma unroll
    for (int o = 16; o; o >>= 1) acc += __shfl_down_sync(0xffffffffu, acc, o);
    if (lane == 0) fred[wz] = acc;
    __syncthreads();
    if (tid == 0) {
        float s = 0.0f;
        for (int w = 0; w < 32; w++) s += fred[w];
        s += g_partialC[c * SPL] + g_partialC[c * SPL + 1] + g_partialC[c * SPL + 2];
        g_chLoss[c] = s;
        out[1 + 32768 + c]       = dkey(redu[1]);
        out[1 + 32768 + 128 + c] = dkey(redu[2]);

        __threadfence();
        unsigned t = atomicAdd(&g_arrive, 1u);
        if (t == CCH - 1) {
            __threadfence();
            double s2 = 0.0;
            for (int i = 0; i < CCH; i++) s2 += (double)g_chLoss[i];
            out[0] = (float)(s2 * (0.01 / ((double)CCH * (double)HW)));
            g_arrive = 0;
            __threadfence();
        }
    }
}

extern "C" void kernel_launch(void* const* d_in, const int* in_sizes, int n_in,
                              void* d_out, int out_size)
{
    const float* input = (const float*)d_in[0];
    const float* mask  = (const float*)d_in[1];
    const float* thist = (const float*)d_in[2];
    const float* tmn   = (const float*)d_in[3];
    const float* tmx   = (const float*)d_in[4];
    float* out = (float*)d_out;

    zeroZ<<<128, 1024>>>();
    histA<<<CCH * SPL, 512>>>(input, mask);
    selB<<<CCH, 1024>>>(thist);
    passC<<<CCH * SPL, 512>>>(input, mask, tmn, tmx);
    phaseD<<<CCH, 1024>>>(tmn, tmx, out);
}

// round 16
// speedup vs baseline: 1.6156x; 1.6156x over previous
#include <cuda_runtime.h>
#include <math.h>

#define CCH 128
#define HW    262144        // 512*512
#define NF4   65536         // HW/4
#define SPL   3
#define CHUNK 21846         // ceil(NF4/3)
#define NW15  16384         // packed words (32768 15-bit bins, u16x2)

// static scratch (allocation-free)
__device__ unsigned int g_cand[(size_t)CCH * HW];
__device__ unsigned int g_hist[(size_t)CCH * NW15];       // 8MB packed u16x2
__device__ unsigned int g_T15[(size_t)CCH * NW15];        // u16[32768] per channel
__device__ unsigned int g_segOff[CCH * 512], g_segLen[CCH * 512];
__device__ unsigned int g_cutBin[CCH * 256], g_cutR[CCH * 256], g_cutSlot[CCH * 256];
__device__ unsigned int g_kbA[CCH * 256], g_bSlot[CCH * 256], g_bPre[CCH * 256];
__device__ unsigned int g_kminA[CCH], g_kmaxA[CCH];
__device__ unsigned int g_tot[CCH];
__device__ float g_partialC[CCH];
__device__ float g_chLoss[CCH];
__device__ unsigned int g_arrive = 0;

__device__ __forceinline__ unsigned int fkey(float x) {
    unsigned int u = __float_as_uint(x);
    return (u & 0x80000000u) ? ~u : (u | 0x80000000u);
}
__device__ __forceinline__ float dkey(unsigned int k) {
    return __uint_as_float((k & 0x80000000u) ? (k & 0x7fffffffu) : ~k);
}
__device__ __forceinline__ int binf(unsigned int k, float mn, float dd) {
    float v = dkey(k);
    float u = (v - mn) / dd;
    int b = (int)(u * 255.0f);
    return b < 0 ? 0 : (b > 255 ? 255 : b);
}
__device__ __forceinline__ unsigned cnt15(const unsigned* H, unsigned b) {
    unsigned w = H[b >> 1];
    return (b & 1) ? (w >> 16) : (w & 0xffffu);
}

// ---------------- Z: zero merged hist + init min/max ----------------
__global__ void zeroH() {
    unsigned i = blockIdx.x * 1024u + threadIdx.x;          // 512*1024 threads
    ((uint4*)g_hist)[i] = make_uint4(0u, 0u, 0u, 0u);       // 8MB
    if (i < CCH) { g_kminA[i] = 0xffffffffu; g_kmaxA[i] = 0u; }
}

// ---------------- A: per-third 15-bit packed histogram + min/max ----------------
__global__ void __launch_bounds__(512, 3)
histA(const float* __restrict__ input, const float* __restrict__ mask)
{
    extern __shared__ unsigned int smem[];
    unsigned int* H   = smem;          // NW15 words (64KB)
    unsigned int* red = smem + NW15;   // 32

    const int bid = blockIdx.x, c = bid / SPL, q = bid - c * SPL;
    const int tid = threadIdx.x, lane = tid & 31, wz = tid >> 5;
    const float4* in4 = (const float4*)(input + (size_t)c * HW);
    const float4* mk4 = (const float4*)mask;

    for (int i = tid; i < NW15; i += 512) H[i] = 0;
    __syncthreads();

    const int start = q * CHUNK;
    const int end = min(start + CHUNK, NF4);
    unsigned kmin = 0xffffffffu, kmax = 0u;
    int i = start + tid;
    for (; i + 512 < end; i += 1024) {
        float4 a0 = in4[i], a1 = in4[i + 512];
        float4 m0 = mk4[i], m1 = mk4[i + 512];
        unsigned k0 = fkey(a0.x * m0.x), k1 = fkey(a0.y * m0.y);
        unsigned k2 = fkey(a0.z * m0.z), k3 = fkey(a0.w * m0.w);
        unsigned k4 = fkey(a1.x * m1.x), k5 = fkey(a1.y * m1.y);
        unsigned k6 = fkey(a1.z * m1.z), k7 = fkey(a1.w * m1.w);
        kmin = min(kmin, min(min(min(k0, k1), min(k2, k3)), min(min(k4, k5), min(k6, k7))));
        kmax = max(kmax, max(max(max(k0, k1), max(k2, k3)), max(max(k4, k5), max(k6, k7))));
        atomicAdd(&H[k0 >> 18], 1u << ((k0 >> 13) & 16));
        atomicAdd(&H[k1 >> 18], 1u << ((k1 >> 13) & 16));
        atomicAdd(&H[k2 >> 18], 1u << ((k2 >> 13) & 16));
        atomicAdd(&H[k3 >> 18], 1u << ((k3 >> 13) & 16));
        atomicAdd(&H[k4 >> 18], 1u << ((k4 >> 13) & 16));
        atomicAdd(&H[k5 >> 18], 1u << ((k5 >> 13) & 16));
        atomicAdd(&H[k6 >> 18], 1u << ((k6 >> 13) & 16));
        atomicAdd(&H[k7 >> 18], 1u << ((k7 >> 13) & 16));
    }
    for (; i < end; i += 512) {
        float4 a = in4[i], m = mk4[i];
        unsigned k0 = fkey(a.x * m.x), k1 = fkey(a.y * m.y);
        unsigned k2 = fkey(a.z * m.z), k3 = fkey(a.w * m.w);
        kmin = min(kmin, min(min(k0, k1), min(k2, k3)));
        kmax = max(kmax, max(max(k0, k1), max(k2, k3)));
        atomicAdd(&H[k0 >> 18], 1u << ((k0 >> 13) & 16));
        atomicAdd(&H[k1 >> 18], 1u << ((k1 >> 13) & 16));
        atomicAdd(&H[k2 >> 18], 1u << ((k2 >> 13) & 16));
        atomicAdd(&H[k3 >> 18], 1u << ((k3 >> 13) & 16));
    }
    #pragma unroll
    for (int o = 16; o; o >>= 1) {
        kmin = min(kmin, __shfl_down_sync(0xffffffffu, kmin, o));
        kmax = max(kmax, __shfl_down_sync(0xffffffffu, kmax, o));
    }
    if (lane == 0) { red[wz] = kmin; red[16 + wz] = kmax; }   // 16 warps
    __syncthreads();
    if (tid == 0) {
        unsigned mn = red[0], mx = red[16];
        for (int w = 1; w < 16; w++) { mn = min(mn, red[w]); mx = max(mx, red[16 + w]); }
        atomicMin(&g_kminA[c], mn);
        atomicMax(&g_kmaxA[c], mx);
    }
    __syncthreads();
    // merge: packed add is carry-safe (per-bin channel totals << 65536)
    for (int j = tid; j < NW15; j += 512) {
        unsigned v = H[j];
        if (v) atomicAdd(&g_hist[(size_t)c * NW15 + j], v);   // RED
    }
}

// ---------------- B: selection per channel (15-bit bins, 17-bit suffix) ----------------
__global__ void __launch_bounds__(1024, 1)
selB(const float* __restrict__ thist)
{
    extern __shared__ unsigned int smem[];
    unsigned int* HIST  = smem;             // NW15
    unsigned int* cutBin = smem + NW15;     // 256
    unsigned int* cutR  = cutBin + 256;     // 256
    unsigned int* kbA   = cutR + 256;       // 256
    unsigned int* bPre  = kbA + 256;        // 256
    unsigned int* Karr  = bPre + 256;       // 256
    unsigned int* uniqB = Karr + 256;       // 512
    unsigned int* segOff = uniqB + 512;     // 512
    unsigned int* segLen = segOff + 512;    // 512
    unsigned int* sgrp  = segLen + 512;     // 257
    float*        cdf   = (float*)(sgrp + 257); // 256
    unsigned int* red   = (unsigned int*)(cdf + 256);  // 8

    const int c = blockIdx.x, tid = threadIdx.x;
    for (int i = tid; i < NW15; i += 1024) HIST[i] = g_hist[(size_t)c * NW15 + i];
    if (tid == 0) { red[0] = g_kminA[c]; red[1] = g_kmaxA[c]; }
    __syncthreads();

    // 256 groups of 128 bins (64 words)
    if (tid >= 64 && tid < 320) {
        int g = tid - 64;
        unsigned s = 0;
        for (int w = 0; w < 64; w++) {
            unsigned v = HIST[g * 64 + w];
            s += (v & 0xffffu) + (v >> 16);
        }
        sgrp[g] = s;
    } else if (tid == 32) {
        float s = 0.0f;
        for (int j = 0; j < 256; j++) { s += thist[c * 256 + j]; cdf[j] = s; }
        float tot = s;
        for (int j = 0; j < 256; j++) {
            float t = (cdf[j] / tot) * 262144.0f;
            float f = floorf(t);
            if (f < 0.0f) f = 0.0f;
            if (f > 262144.0f) f = 262144.0f;
            Karr[j] = (unsigned)f;
        }
    }
    __syncthreads();
    if (tid == 0) {
        unsigned acc = 0;
        for (int g = 0; g < 256; g++) { unsigned t = sgrp[g]; sgrp[g] = acc; acc += t; }
        sgrp[256] = acc;
    }
    __syncthreads();

    // cut bins + boundary keys
    if (tid < 256) {
        unsigned k = Karr[tid];
        if (k == 0) { cutBin[tid] = 0xffffffffu; cutR[tid] = 0; }
        else {
            int lo = 0, hi = 255;
            while (lo < hi) { int mid = (lo + hi + 1) >> 1; if (sgrp[mid] < k) lo = mid; else hi = mid - 1; }
            unsigned acc = sgrp[lo];
            unsigned bin = (unsigned)lo * 128u;
            for (;; bin++) { unsigned ct = cnt15(HIST, bin); if (acc + ct >= k) break; acc += ct; }
            cutBin[tid] = bin;
            cutR[tid] = k - acc;
        }
    } else if (tid < 511) {
        int j = tid - 255;
        unsigned mnk = red[0], mxk = red[1];
        float mn = dkey(mnk), mx = dkey(mxk);
        float dd = fmaxf(mx - mn, 1e-8f);
        if (binf(mxk, mn, dd) < j) kbA[j] = 0u;
        else {
            unsigned lo = mnk, hi = mxk;
            while (lo < hi) {
                unsigned mid = lo + ((hi - lo) >> 1);
                if (binf(mid, mn, dd) >= j) hi = mid; else lo = mid + 1;
            }
            kbA[j] = lo;
        }
    }
    __syncthreads();

    // boundary prefix counts + merge active bins
    if (tid >= 256 && tid < 511) {
        int j = tid - 255;
        unsigned kb = kbA[j];
        if (kb != 0u) {
            unsigned p = kb >> 17, g = p >> 7;
            unsigned s = sgrp[g];
            for (unsigned b = g << 7; b < p; b++) s += cnt15(HIST, b);
            bPre[j] = s;
        }
    } else if (tid == 0) {
        int i = 0, j = 1, n = 0;
        unsigned off = 0;
        for (;;) {
            unsigned a = 0xffffffffu, b = 0xffffffffu;
            while (i < 256 && cutBin[i] == 0xffffffffu) i++;
            if (i < 256) a = cutBin[i];
            while (j < 256 && kbA[j] == 0u) j++;
            if (j < 256) b = kbA[j] >> 17;
            if (a == 0xffffffffu && b == 0xffffffffu) break;
            unsigned v = min(a, b);
            while (i < 256 && cutBin[i] == v) i++;
            while (j < 256 && kbA[j] != 0u && (kbA[j] >> 17) == v) j++;
            unsigned ct = cnt15(HIST, v);
            uniqB[n] = v; segOff[n] = off; segLen[n] = ct;
            off += ct; n++;
        }
        red[2] = (unsigned)n;
        red[3] = off;
    }
    __syncthreads();
    const int nU = (int)red[2];

    // slots + global writes
    if (tid < 256) {
        unsigned cs = 0;
        if (cutBin[tid] != 0xffffffffu) {
            unsigned p = cutBin[tid];
            int lo = 0, hi = nU - 1;
            while (lo < hi) { int mid = (lo + hi) >> 1; if (uniqB[mid] < p) lo = mid + 1; else hi = mid; }
            cs = (unsigned)lo;
        }
        g_cutBin[c * 256 + tid] = cutBin[tid];
        g_cutR[c * 256 + tid]   = cutR[tid];
        g_cutSlot[c * 256 + tid] = cs;
    } else if (tid < 511) {
        int j = tid - 255;
        unsigned bs = 0;
        if (kbA[j] != 0u) {
            unsigned p = kbA[j] >> 17;
            int lo = 0, hi = nU - 1;
            while (lo < hi) { int mid = (lo + hi) >> 1; if (uniqB[mid] < p) lo = mid + 1; else hi = mid; }
            bs = (unsigned)lo;
        }
        g_kbA[c * 256 + j]   = kbA[j];
        g_bSlot[c * 256 + j] = bs;
        g_bPre[c * 256 + j]  = bPre[j];
    } else if (tid == 511) {
        g_kbA[c * 256] = 0; g_bSlot[c * 256] = 0; g_bPre[c * 256] = 0;
        g_tot[c] = red[3];
    }
    if (tid < 512) {
        g_segOff[c * 512 + tid] = (tid < nU) ? segOff[tid] : 0u;
        g_segLen[c * 512 + tid] = (tid < nU) ? segLen[tid] : 0u;
    }
    __syncthreads();

    // T15 table: 32768 u16 -> 16384 words (each thread: 32 bins = 16 words)
    {
        int p0 = tid * 32;
        int lo = 0, hi = 256;
        while (lo < hi) {
            int mid = (lo + hi) >> 1;
            unsigned cl = (Karr[mid] == 0) ? 0u : cutBin[mid];
            if ((int)cl < p0) lo = mid + 1; else hi = mid;
        }
        int idx = lo;
        #pragma unroll 4
        for (int w = 0; w < 16; w++) {
            unsigned word = 0;
            #pragma unroll
            for (int e = 0; e < 2; e++) {
                int p = p0 + w * 2 + e;
                for (;;) {
                    if (idx >= 256) break;
                    unsigned cl = (Karr[idx] == 0) ? 0u : cutBin[idx];
                    if ((int)cl < p) idx++; else break;
                }
                word |= ((unsigned)min(idx, 255)) << (16 * e);
            }
            g_T15[(size_t)c * NW15 + p0 / 2 + w] = word;
        }
    }
    __syncthreads();
    if (tid < nU)
        ((unsigned short*)g_T15)[(size_t)c * 32768 + uniqB[tid]] = (unsigned short)(0x8000u | (unsigned)tid);
}

// ---------------- C: fused classify -> compact / loss (1 CTA/channel) ----------------
__global__ void __launch_bounds__(1024, 1)
passC(const float* __restrict__ input, const float* __restrict__ mask,
      const float* __restrict__ tmin_, const float* __restrict__ tmax_)
{
    extern __shared__ unsigned int smem[];
    unsigned int* T15s   = smem;            // NW15 words (64KB)
    unsigned int* segOffS = smem + NW15;    // 512
    unsigned int* cursor = segOffS + 512;   // 512
    float*        fred   = (float*)(cursor + 512); // 32

    const int c = blockIdx.x;
    const int tid = threadIdx.x, lane = tid & 31, wz = tid >> 5;

    for (int i = tid; i < NW15; i += 1024) T15s[i] = g_T15[(size_t)c * NW15 + i];
    if (tid < 512) { segOffS[tid] = g_segOff[c * 512 + tid]; cursor[tid] = 0u; }
    __syncthreads();

    const float4* in4 = (const float4*)(input + (size_t)c * HW);
    const float4* mk4 = (const float4*)mask;
    unsigned int* candC = g_cand + (size_t)c * HW;
    const unsigned short* T15 = (const unsigned short*)T15s;

    const float tmn = tmin_[c];
    const float scl = tmax_[c] - tmn;
    float acc = 0.0f;

    #pragma unroll 1
    for (int i = tid; i < NF4; i += 2048) {
        float4 a0 = in4[i], a1 = in4[i + 1024];
        float4 m0 = mk4[i], m1 = mk4[i + 1024];
        float vv[8] = {a0.x * m0.x, a0.y * m0.y, a0.z * m0.z, a0.w * m0.w,
                       a1.x * m1.x, a1.y * m1.y, a1.z * m1.z, a1.w * m1.w};
        #pragma unroll
        for (int e = 0; e < 8; e++) {
            float v = vv[e];
            unsigned key = fkey(v);
            unsigned t = T15[key >> 17];
            if (t & 0x8000u) {
                unsigned s = t & 0x7fffu;
                candC[segOffS[s] + atomicAdd(&cursor[s], 1u)] = key;
            } else {
                float bf = (float)t * (1.0f / 255.0f);
                float df = v - fmaf(bf, scl, tmn);
                acc = fmaf(df, df, acc);
            }
        }
    }
    #pragma unroll
    for (int o = 16; o; o >>= 1) acc += __shfl_down_sync(0xffffffffu, acc, o);
    if (lane == 0) fred[wz] = acc;
    __syncthreads();
    if (tid == 0) {
        float s = 0.0f;
        for (int w = 0; w < 32; w++) s += fred[w];
        g_partialC[c] = s;
    }
}

// ---------------- D: refine (17 suffix bits) + candidate loss + outputs ----------------
__global__ void __launch_bounds__(1024, 1)
phaseD(const float* __restrict__ tmin_, const float* __restrict__ tmax_,
       float* __restrict__ out)
{
    extern __shared__ unsigned int smem[];
    unsigned int* WH     = smem;            // 8192
    unsigned int* cutBin = smem + 8192;     // 256
    unsigned int* cutR   = cutBin + 256;
    unsigned int* cutSlot = cutR + 256;
    unsigned int* kbA    = cutSlot + 256;
    unsigned int* bSlot  = kbA + 256;
    unsigned int* bPre   = bSlot + 256;
    unsigned int* thA    = bPre + 256;
    unsigned int* rankA  = thA + 256;       // 257
    unsigned int* segOff = rankA + 257;     // 512
    unsigned int* segLen = segOff + 512;    // 512
    float*        fred   = (float*)(segLen + 512);  // 32
    unsigned int* redu   = (unsigned int*)(fred + 32); // 4

    const int c = blockIdx.x, tid = threadIdx.x, lane = tid & 31, wz = tid >> 5;
    unsigned int* candC = g_cand + (size_t)c * HW;

    if (tid < 256) {
        cutBin[tid] = g_cutBin[c * 256 + tid];
        cutR[tid]   = g_cutR[c * 256 + tid];
        cutSlot[tid] = g_cutSlot[c * 256 + tid];
        kbA[tid]   = g_kbA[c * 256 + tid];
        bSlot[tid] = g_bSlot[c * 256 + tid];
        bPre[tid]  = g_bPre[c * 256 + tid];
        thA[tid] = 0u;
    }
    if (tid < 512) { segOff[tid] = g_segOff[c * 512 + tid]; segLen[tid] = g_segLen[c * 512 + tid]; }
    if (tid < 257) rankA[tid] = (tid == 0) ? 0u : (unsigned)HW;
    if (tid == 0) { redu[0] = g_tot[c]; redu[1] = g_kminA[c]; redu[2] = g_kmaxA[c]; }
    __syncthreads();

    {
        unsigned* wh = WH + wz * 256;
        for (int q = wz; q < 511; q += 32) {
            if (q < 256) {
                if (cutBin[q] == 0xffffffffu) continue;
                unsigned slot = cutSlot[q];
                unsigned off = segOff[slot], len = segLen[slot], r = cutR[q];
                unsigned known = cutBin[q];
                // rounds over 17 suffix bits: widths 8, 8, 1
                #pragma unroll
                for (int t = 0; t < 3; t++) {
                    const int s  = (t == 0) ? 9 : (t == 1) ? 1 : 0;
                    const int w  = (t == 2) ? 1 : 8;
                    const unsigned nb = 1u << w;
                    for (unsigned i2 = lane; i2 < nb; i2 += 32) wh[i2] = 0;
                    __syncwarp();
                    for (unsigned i2 = lane; i2 < len; i2 += 32) {
                        unsigned key = candC[off + i2];
                        if ((key >> (s + w)) == known)
                            atomicAdd(&wh[(key >> s) & (nb - 1u)], 1u);
                    }
                    __syncwarp();
                    unsigned sel = 0, rem = 0;
                    if (lane == 0) {
                        unsigned a2 = 0; unsigned b = 0;
                        for (;; b++) { unsigned ct = wh[b]; if (a2 + ct >= r) break; a2 += ct; }
                        sel = b; rem = r - a2;
                    }
                    sel = __shfl_sync(0xffffffffu, sel, 0);
                    rem = __shfl_sync(0xffffffffu, rem, 0);
                    known = (known << w) | sel;
                    r = rem;
                    __syncwarp();
                }
                if (lane == 0) thA[q] = known;
            } else {
                int j = q - 255;
                if (kbA[j] == 0u) continue;
                unsigned slot = bSlot[j];
                unsigned off = segOff[slot], len = segLen[slot];
                unsigned bs = kbA[j] & 0x1ffffu;
                unsigned cnt = 0;
                for (unsigned i2 = lane; i2 < len; i2 += 32)
                    cnt += ((candC[off + i2] & 0x1ffffu) < bs) ? 1u : 0u;
                #pragma unroll
                for (int o = 16; o; o >>= 1) cnt += __shfl_down_sync(0xffffffffu, cnt, o);
                if (lane == 0) rankA[j] = bPre[j] + cnt;
            }
        }
    }
    __syncthreads();

    const float tmn = tmin_[c];
    const float scl = tmax_[c] - tmn;
    float acc = 0.0f;
    {
        const int tot = (int)redu[0];
        for (int i = tid; i < tot; i += 1024) {
            unsigned key = candC[i];
            int lo = 0, hi = 256;
            while (lo < hi) { int mid = (lo + hi) >> 1; if (thA[mid] < key) lo = mid + 1; else hi = mid; }
            int bm = min(lo, 255);
            float v = dkey(key);
            float bf = (float)bm * (1.0f / 255.0f);
            float df = v - fmaf(bf, scl, tmn);
            acc = fmaf(df, df, acc);
        }
    }

    if (tid < 256) out[1 + c * 256 + tid] = (float)(rankA[tid + 1] - rankA[tid]);

    #pragma unroll
    for (int o = 16; o; o >>= 1) acc += __shfl_down_sync(0xffffffffu, acc, o);
    if (lane == 0) fred[wz] = acc;
    __syncthreads();
    if (tid == 0) {
        float s = 0.0f;
        for (int w = 0; w < 32; w++) s += fred[w];
        s += g_partialC[c];
        g_chLoss[c] = s;
        out[1 + 32768 + c]       = dkey(redu[1]);
        out[1 + 32768 + 128 + c] = dkey(redu[2]);

        __threadfence();
        unsigned t = atomicAdd(&g_arrive, 1u);
        if (t == CCH - 1) {
            __threadfence();
            double s2 = 0.0;
            for (int i = 0; i < CCH; i++) s2 += (double)g_chLoss[i];
            out[0] = (float)(s2 * (0.01 / ((double)CCH * (double)HW)));
            g_arrive = 0;
            __threadfence();
        }
    }
}

extern "C" void kernel_launch(void* const* d_in, const int* in_sizes, int n_in,
                              void* d_out, int out_size)
{
    const float* input = (const float*)d_in[0];
    const float* mask  = (const float*)d_in[1];
    const float* thist = (const float*)d_in[2];
    const float* tmn   = (const float*)d_in[3];
    const float* tmx   = (const float*)d_in[4];
    float* out = (float*)d_out;

    const int smA = (NW15 + 32) * 4;
    const int smB = (NW15 + 256 * 5 + 512 * 3 + 257 + 256 + 8 + 64) * 4;
    const int smC = (NW15 + 512 + 512 + 32 + 8) * 4;
    const int smD = (8192 + 256 * 7 + 257 + 512 * 2 + 32 + 8) * 4;

    cudaFuncSetAttribute(histA,  cudaFuncAttributeMaxDynamicSharedMemorySize, smA);
    cudaFuncSetAttribute(selB,   cudaFuncAttributeMaxDynamicSharedMemorySize, smB);
    cudaFuncSetAttribute(passC,  cudaFuncAttributeMaxDynamicSharedMemorySize, smC);
    cudaFuncSetAttribute(phaseD, cudaFuncAttributeMaxDynamicSharedMemorySize, smD);

    zeroH<<<512, 1024>>>();
    histA<<<CCH * SPL, 512, smA>>>(input, mask);
    selB<<<CCH, 1024, smB>>>(thist);
    passC<<<CCH, 1024, smC>>>(input, mask, tmn, tmx);
    phaseD<<<CCH, 1024, smD>>>(tmn, tmx, out);
}